// round 16
// baseline (speedup 1.0000x reference)
#include <cuda_runtime.h>
#include <cuda_bf16.h>
#include <math.h>
#include <stdint.h>

// ---------------- problem dims ----------------
#define NB 8
#define TT 2048
#define DD 1024
#define HH 1536
#define GG 3072              // 2*H
#define MM (NB*TT)           // 16384
#define NCHUNK 16
#define CLEN (TT/NCHUNK)     // 128

// ---------------- scratch ----------------
__device__ float g_u[(size_t)MM*GG];        // u = x @ W_in^T  (gate | xh)
__device__ float g_xc[(size_t)MM*HH];       // conv output fp32
__device__ float g_gp[(size_t)MM*GG];       // gates GEMM out, permuted pairs (forget,inp)
__device__ float2 g_axs[(size_t)MM*HH];     // interleaved (alpha, xs)
__device__ float g_sp[HH];                  // softplus(forget_base)
__device__ float g_carryA[NB*NCHUNK*HH];
__device__ float g_carryH[NB*NCHUNK*HH];
__device__ float g_chunkIn[NB*NCHUNK*HH];
// split-bf16 operand buffers
__device__ __nv_bfloat16 g_ahi[(size_t)MM*HH];
__device__ __nv_bfloat16 g_alo[(size_t)MM*HH];
__device__ __nv_bfloat16 g_bhi[(size_t)GG*HH];
__device__ __nv_bfloat16 g_blo[(size_t)GG*HH];

// ---------------- PTX helpers ----------------
__device__ __forceinline__ uint32_t smem_u32(const void* p) {
    uint32_t a;
    asm("{ .reg .u64 t; cvta.to.shared.u64 t, %1; cvt.u32.u64 %0, t; }" : "=r"(a) : "l"(p));
    return a;
}
__device__ __forceinline__ void ldsm_x4(uint32_t& r0, uint32_t& r1, uint32_t& r2, uint32_t& r3,
                                        uint32_t addr) {
    asm volatile("ldmatrix.sync.aligned.m8n8.x4.shared.b16 {%0,%1,%2,%3}, [%4];"
                 : "=r"(r0), "=r"(r1), "=r"(r2), "=r"(r3) : "r"(addr));
}
__device__ __forceinline__ void mma16816(float* c,
                                         uint32_t a0, uint32_t a1, uint32_t a2, uint32_t a3,
                                         uint32_t b0, uint32_t b1) {
    asm volatile(
        "mma.sync.aligned.m16n8k16.row.col.f32.bf16.bf16.f32 "
        "{%0,%1,%2,%3}, {%4,%5,%6,%7}, {%8,%9}, {%0,%1,%2,%3};"
        : "+f"(c[0]), "+f"(c[1]), "+f"(c[2]), "+f"(c[3])
        : "r"(a0), "r"(a1), "r"(a2), "r"(a3), "r"(b0), "r"(b1));
}
__device__ __forceinline__ void cp_async16(uint32_t saddr, const void* g) {
    asm volatile("cp.async.cg.shared.global [%0], [%1], 16;" :: "r"(saddr), "l"(g));
}
__device__ __forceinline__ void cp_commit() { asm volatile("cp.async.commit_group;"); }
template<int N> __device__ __forceinline__ void cp_wait() {
    asm volatile("cp.async.wait_group %0;" :: "n"(N));
}

// ---------------- split-bf16 TN GEMM: kc-major fused 3-term ----------------
// per BK=32 chunk: stage {Ahi, Alo, Bhi, Blo}; per kk batch-load B frags + Ahi
// frags (8 ldsm), 32 mma; reload A frags with Alo, 16 mma.  12 ldsm : 48 mma.
// block 128x128, 256 threads = 8 warps (2 M x 4 N), warp tile 64x32
// 2-stage cp.async ring, 1 sync per chunk, 2 CTA/SM
#define BM 128
#define BN 128
#define BK 32
#define SSTR 40                          // smem row stride in bf16 (32 + 8 pad)
#define TILE_BYTES (BM*SSTR*2)           // 10240
#define STAGE_BYTES (4*TILE_BYTES)       // 40960
#define SMEM_BYTES (2*STAGE_BYTES)       // 81920

__device__ __forceinline__ void tn_gemm_body(
    const __nv_bfloat16* __restrict__ Ahi, const __nv_bfloat16* __restrict__ Alo,
    const __nv_bfloat16* __restrict__ Bhi, const __nv_bfloat16* __restrict__ Blo,
    float* __restrict__ C, int Ndim, int Kdim)
{
    extern __shared__ __nv_bfloat16 smem[];

    const int tid = threadIdx.x;
    const int wid = tid >> 5;
    const int lane = tid & 31;
    const int warp_m = wid >> 2;       // 0..1
    const int warp_n = wid & 3;        // 0..3
    const int m0 = blockIdx.y * BM;
    const int n0 = blockIdx.x * BN;

    // loader: per tile 512 uint4 (128 rows x 4); 256 threads -> rows lr, lr+64
    const int lr = tid >> 2;           // 0..63
    const int q0 = tid & 3;
    const uint32_t smem_base = smem_u32(smem);
    const uint32_t soff0 = (uint32_t)((lr      ) * SSTR + q0 * 8) * 2;
    const uint32_t soff1 = (uint32_t)((lr + 64) * SSTR + q0 * 8) * 2;

    float acc[4][4][4];
#pragma unroll
    for (int i = 0; i < 4; i++)
#pragma unroll
        for (int j = 0; j < 4; j++)
#pragma unroll
            for (int v = 0; v < 4; v++) acc[i][j][v] = 0.f;

    const int kcs = Kdim / BK;

    auto issue = [&](int kc) {
        if (kc < kcs) {
            const uint32_t sbase = smem_base + (uint32_t)(kc & 1) * STAGE_BYTES;
            const __nv_bfloat16* srcs[4] = {
                Ahi + (size_t)m0 * Kdim + kc * BK + q0 * 8,
                Alo + (size_t)m0 * Kdim + kc * BK + q0 * 8,
                Bhi + (size_t)n0 * Kdim + kc * BK + q0 * 8,
                Blo + (size_t)n0 * Kdim + kc * BK + q0 * 8
            };
#pragma unroll
            for (int t = 0; t < 4; t++) {
                cp_async16(sbase + (uint32_t)t * TILE_BYTES + soff0,
                           srcs[t] + (size_t)lr * Kdim);
                cp_async16(sbase + (uint32_t)t * TILE_BYTES + soff1,
                           srcs[t] + (size_t)(lr + 64) * Kdim);
            }
        }
        cp_commit();
    };

    // fragment offsets (bytes within a tile)
    const uint32_t afrag = (uint32_t)(((warp_m * 64 + (lane & 15)) * SSTR
                                       + (lane >> 4) * 8) * 2);
    const uint32_t bfrag = (uint32_t)(((warp_n * 32 + (lane & 15)) * SSTR
                                       + (lane >> 4) * 8) * 2);

    issue(0);

    for (int kc = 0; kc < kcs; kc++) {
        cp_wait<0>();          // stage kc landed
        __syncthreads();       // all warps past compute(kc-1) before reusing its buffer
        issue(kc + 1);

        const uint32_t sbase = smem_base + (uint32_t)(kc & 1) * STAGE_BYTES;
        const uint32_t sAhi = sbase + 0 * TILE_BYTES;
        const uint32_t sAlo = sbase + 1 * TILE_BYTES;
        const uint32_t sBhi = sbase + 2 * TILE_BYTES;
        const uint32_t sBlo = sbase + 3 * TILE_BYTES;

#pragma unroll
        for (int kk = 0; kk < 2; kk++) {
            const uint32_t koff = (uint32_t)(kk * 32);   // 16 bf16 = 32 bytes
            uint32_t bh[2][4], bl[2][4];
#pragma unroll
            for (int nb = 0; nb < 2; nb++) {
                ldsm_x4(bh[nb][0], bh[nb][1], bh[nb][2], bh[nb][3],
                        sBhi + bfrag + (uint32_t)(nb * 16 * SSTR * 2) + koff);
                ldsm_x4(bl[nb][0], bl[nb][1], bl[nb][2], bl[nb][3],
                        sBlo + bfrag + (uint32_t)(nb * 16 * SSTR * 2) + koff);
            }
            uint32_t a[4][4];
#pragma unroll
            for (int mi = 0; mi < 4; mi++)
                ldsm_x4(a[mi][0], a[mi][1], a[mi][2], a[mi][3],
                        sAhi + afrag + (uint32_t)(mi * 16 * SSTR * 2) + koff);
            // Ahi * Bhi  and  Ahi * Blo  (32 mma, all fragments resident)
#pragma unroll
            for (int mi = 0; mi < 4; mi++) {
#pragma unroll
                for (int nb = 0; nb < 2; nb++) {
                    mma16816(acc[mi][nb * 2 + 0], a[mi][0], a[mi][1], a[mi][2], a[mi][3],
                             bh[nb][0], bh[nb][2]);
                    mma16816(acc[mi][nb * 2 + 1], a[mi][0], a[mi][1], a[mi][2], a[mi][3],
                             bh[nb][1], bh[nb][3]);
                    mma16816(acc[mi][nb * 2 + 0], a[mi][0], a[mi][1], a[mi][2], a[mi][3],
                             bl[nb][0], bl[nb][2]);
                    mma16816(acc[mi][nb * 2 + 1], a[mi][0], a[mi][1], a[mi][2], a[mi][3],
                             bl[nb][1], bl[nb][3]);
                }
            }
            // Alo * Bhi  (reload A frags, 16 mma)
#pragma unroll
            for (int mi = 0; mi < 4; mi++)
                ldsm_x4(a[mi][0], a[mi][1], a[mi][2], a[mi][3],
                        sAlo + afrag + (uint32_t)(mi * 16 * SSTR * 2) + koff);
#pragma unroll
            for (int mi = 0; mi < 4; mi++) {
#pragma unroll
                for (int nb = 0; nb < 2; nb++) {
                    mma16816(acc[mi][nb * 2 + 0], a[mi][0], a[mi][1], a[mi][2], a[mi][3],
                             bh[nb][0], bh[nb][2]);
                    mma16816(acc[mi][nb * 2 + 1], a[mi][0], a[mi][1], a[mi][2], a[mi][3],
                             bh[nb][1], bh[nb][3]);
                }
            }
        }
    }

    // ---- epilogue: plain coalesced store ----
    const int crow0 = m0 + warp_m * 64 + (lane >> 2);
    const int ccol0 = n0 + warp_n * 32 + (lane & 3) * 2;
#pragma unroll
    for (int mi = 0; mi < 4; mi++) {
#pragma unroll
        for (int ni = 0; ni < 4; ni++) {
            int row = crow0 + mi * 16;
            int col = ccol0 + ni * 8;
            float2 v0, v1;
            v0.x = acc[mi][ni][0]; v0.y = acc[mi][ni][1];
            v1.x = acc[mi][ni][2]; v1.y = acc[mi][ni][3];
            *(float2*)(C + (size_t)row * Ndim + col)       = v0;
            *(float2*)(C + (size_t)(row + 8) * Ndim + col) = v1;
        }
    }
}

__global__ __launch_bounds__(256, 2) void tcgemm_in()
{
    tn_gemm_body(g_ahi, g_alo, g_bhi, g_blo, g_u, GG, DD);
}
__global__ __launch_bounds__(256, 2) void tcgemm_gates()
{
    tn_gemm_body(g_ahi, g_alo, g_bhi, g_blo, g_gp, GG, HH);
}
__global__ __launch_bounds__(256, 2) void tcgemm_out(float* __restrict__ out)
{
    tn_gemm_body(g_ahi, g_alo, g_bhi, g_blo, out, DD, HH);
}

// ---------------- fp32 -> (hi, lo) bf16 split ----------------
__device__ __forceinline__ void split1(float v, __nv_bfloat16& hi, __nv_bfloat16& lo) {
    __nv_bfloat16 h = __float2bfloat16(v);
    hi = h;
    lo = __float2bfloat16(v - __bfloat162float(h));
}
__global__ __launch_bounds__(256) void split_x(const float* __restrict__ x, int n4)
{
    int id = blockIdx.x * blockDim.x + threadIdx.x;
    if (id >= n4) return;
    float4 v = ((const float4*)x)[id];
    __nv_bfloat16 h0, h1, h2, h3, l0, l1, l2, l3;
    split1(v.x, h0, l0); split1(v.y, h1, l1);
    split1(v.z, h2, l2); split1(v.w, h3, l3);
    ((__nv_bfloat162*)g_ahi)[id * 2 + 0] = __nv_bfloat162(h0, h1);
    ((__nv_bfloat162*)g_ahi)[id * 2 + 1] = __nv_bfloat162(h2, h3);
    ((__nv_bfloat162*)g_alo)[id * 2 + 0] = __nv_bfloat162(l0, l1);
    ((__nv_bfloat162*)g_alo)[id * 2 + 1] = __nv_bfloat162(l2, l3);
}
__global__ __launch_bounds__(256) void split_w(const float* __restrict__ w, int n4)
{
    int id = blockIdx.x * blockDim.x + threadIdx.x;
    if (id >= n4) return;
    float4 v = ((const float4*)w)[id];
    __nv_bfloat16 h0, h1, h2, h3, l0, l1, l2, l3;
    split1(v.x, h0, l0); split1(v.y, h1, l1);
    split1(v.z, h2, l2); split1(v.w, h3, l3);
    ((__nv_bfloat162*)g_bhi)[id * 2 + 0] = __nv_bfloat162(h0, h1);
    ((__nv_bfloat162*)g_bhi)[id * 2 + 1] = __nv_bfloat162(h2, h3);
    ((__nv_bfloat162*)g_blo)[id * 2 + 0] = __nv_bfloat162(l0, l1);
    ((__nv_bfloat162*)g_blo)[id * 2 + 1] = __nv_bfloat162(l2, l3);
}
// permuted split for W_gates: dst row 2h = W_gates row h (forget), 2h+1 = row HH+h (inp)
__global__ __launch_bounds__(256) void split_w_gates(const float* __restrict__ w, int n4)
{
    int id = blockIdx.x * blockDim.x + threadIdx.x;
    if (id >= n4) return;
    int e = id * 4;
    int j = e / HH;                    // dst row
    int o = e - j * HH;
    int src = (j & 1) ? (HH + (j >> 1)) : (j >> 1);
    float4 v = *(const float4*)(w + (size_t)src * HH + o);
    __nv_bfloat16 h0, h1, h2, h3, l0, l1, l2, l3;
    split1(v.x, h0, l0); split1(v.y, h1, l1);
    split1(v.z, h2, l2); split1(v.w, h3, l3);
    ((__nv_bfloat162*)g_bhi)[id * 2 + 0] = __nv_bfloat162(h0, h1);
    ((__nv_bfloat162*)g_bhi)[id * 2 + 1] = __nv_bfloat162(h2, h3);
    ((__nv_bfloat162*)g_blo)[id * 2 + 0] = __nv_bfloat162(l0, l1);
    ((__nv_bfloat162*)g_blo)[id * 2 + 1] = __nv_bfloat162(l2, l3);
}
__global__ __launch_bounds__(256) void prep_sp(const float* __restrict__ fb)
{
    int i = blockIdx.x * blockDim.x + threadIdx.x;
    if (i < HH) g_sp[i] = log1pf(expf(fb[i]));
}

// ---------------- causal depthwise conv: 4 timesteps/thread, fused split -------
__global__ __launch_bounds__(256) void conv4_kernel(
    const float* __restrict__ cw, const float* __restrict__ cb)
{
    int id = blockIdx.x * blockDim.x + threadIdx.x;
    if (id >= (MM / 4) * HH) return;
    int h = id % HH;
    int g = id / HH;                   // 0 .. MM/4-1
    int tq = g % (TT / 4);
    int n  = g / (TT / 4);
    int t0 = tq * 4;
    const size_t mrow = (size_t)n * TT;

    float w0 = cw[h * 4 + 0], w1 = cw[h * 4 + 1];
    float w2 = cw[h * 4 + 2], w3 = cw[h * 4 + 3];
    float bb = cb[h];

    float xv[7];
#pragma unroll
    for (int j = 0; j < 7; j++) {
        int t = t0 - 3 + j;
        xv[j] = (t >= 0) ? g_u[(mrow + t) * GG + HH + h] : 0.f;
    }
#pragma unroll
    for (int i = 0; i < 4; i++) {
        float acc = bb + w0 * xv[i] + w1 * xv[i + 1] + w2 * xv[i + 2] + w3 * xv[i + 3];
        size_t idx = (mrow + t0 + i) * HH + h;
        g_xc[idx] = acc;
        __nv_bfloat16 hi, lo;
        split1(acc, hi, lo);
        g_ahi[idx] = hi;
        g_alo[idx] = lo;
    }
}

// ---------------- scan pass 1 with FUSED gate math ----------------
__global__ __launch_bounds__(256) void scan1_gate_kernel(const float* __restrict__ b_gates)
{
    int id = blockIdx.x * blockDim.x + threadIdx.x;
    if (id >= NB * NCHUNK * HH) return;
    int h = id % HH;
    int r = id / HH;
    int c = r % NCHUNK;
    int n = r / NCHUNK;

    const float bf_ = b_gates[h];
    const float bi_ = b_gates[HH + h];
    const float sp8 = -8.f * g_sp[h];

    float arun = 1.f, hrun = 0.f;
    size_t m0 = (size_t)n * TT + c * CLEN;
#pragma unroll 2
    for (int tl = 0; tl < CLEN; tl++) {
        size_t m = m0 + tl;
        float2 fi = ((const float2*)(g_gp + m * GG))[h];   // (forget, inp)
        float f  = fi.x + bf_;
        float iv = fi.y + bi_;
        float sf = 1.f / (1.f + expf(-f));
        float alpha = expf(sp8 * sf);
        float beta  = sqrtf(1.f - alpha * alpha + 1e-6f);
        float si = 1.f / (1.f + expf(-iv));
        size_t idx = m * HH + h;
        float xs = beta * si * g_xc[idx];
        g_axs[idx] = make_float2(alpha, xs);
        hrun = alpha * hrun + xs;
        arun *= alpha;
    }
    g_carryA[id] = arun;
    g_carryH[id] = hrun;
}
__global__ __launch_bounds__(256) void scan2_kernel()
{
    int id = blockIdx.x * blockDim.x + threadIdx.x;
    if (id >= NB * HH) return;
    int h = id % HH;
    int n = id / HH;
    float hin = 0.f;
    for (int c = 0; c < NCHUNK; c++) {
        int j = (n * NCHUNK + c) * HH + h;
        g_chunkIn[j] = hin;
        hin = g_carryA[j] * hin + g_carryH[j];
    }
}
__global__ __launch_bounds__(256) void scan3_kernel()
{
    int id = blockIdx.x * blockDim.x + threadIdx.x;
    if (id >= NB * NCHUNK * HH) return;
    int h = id % HH;
    int r = id / HH;
    int c = r % NCHUNK;
    int n = r / NCHUNK;
    float hrun = g_chunkIn[(n * NCHUNK + c) * HH + h];
    size_t m0 = (size_t)n * TT + c * CLEN;
#pragma unroll 4
    for (int tl = 0; tl < CLEN; tl++) {
        size_t m = m0 + tl;
        size_t idx = m * HH + h;
        float2 ax = g_axs[idx];
        hrun = ax.x * hrun + ax.y;
        float gate = g_u[m * GG + h];
        float ge = 0.5f * gate * (1.f + erff(gate * 0.70710678118654752f));
        float v = ge * hrun;
        __nv_bfloat16 hi, lo;
        split1(v, hi, lo);
        g_ahi[idx] = hi;
        g_alo[idx] = lo;
    }
}

// ---------------- launch ----------------
extern "C" void kernel_launch(void* const* d_in, const int* in_sizes, int n_in,
                              void* d_out, int out_size)
{
    const float* x          = (const float*)d_in[0];
    const float* W_in       = (const float*)d_in[1];
    const float* conv_w     = (const float*)d_in[2];
    const float* conv_b     = (const float*)d_in[3];
    const float* W_gates    = (const float*)d_in[4];
    const float* b_gates    = (const float*)d_in[5];
    const float* forget_b   = (const float*)d_in[6];
    const float* W_out      = (const float*)d_in[7];
    float* out = (float*)d_out;

    // allow >48KB dynamic smem (device-state change, not graph work)
    cudaFuncSetAttribute(tcgemm_in,    cudaFuncAttributeMaxDynamicSharedMemorySize, SMEM_BYTES);
    cudaFuncSetAttribute(tcgemm_gates, cudaFuncAttributeMaxDynamicSharedMemorySize, SMEM_BYTES);
    cudaFuncSetAttribute(tcgemm_out,   cudaFuncAttributeMaxDynamicSharedMemorySize, SMEM_BYTES);

    // 1) splits + softplus precompute
    split_x<<<(MM * DD / 4 + 255) / 256, 256>>>(x, MM * DD / 4);
    split_w<<<(GG * DD / 4 + 255) / 256, 256>>>(W_in, GG * DD / 4);
    prep_sp<<<(HH + 255) / 256, 256>>>(forget_b);
    // 2) u = x @ W_in^T
    {
        dim3 grid(GG / BN, MM / BM);
        tcgemm_in<<<grid, 256, SMEM_BYTES>>>();
    }
    // 3) causal conv (4 timesteps per thread)
    conv4_kernel<<<((MM / 4) * HH + 255) / 256, 256>>>(conv_w, conv_b);
    split_w_gates<<<(GG * HH / 4 + 255) / 256, 256>>>(W_gates, GG * HH / 4);
    // 4) gates GEMM (permuted pairs)
    {
        dim3 grid(GG / BN, MM / BM);
        tcgemm_gates<<<grid, 256, SMEM_BYTES>>>();
    }
    // 5) chunked scan: pass1 fuses gate math; combine; recompute+gelu+split
    scan1_gate_kernel<<<(NB * NCHUNK * HH) / 256, 256>>>(b_gates);
    scan2_kernel<<<(NB * HH + 255) / 256, 256>>>();
    scan3_kernel<<<(NB * NCHUNK * HH) / 256, 256>>>();
    split_w<<<(DD * HH / 4 + 255) / 256, 256>>>(W_out, DD * HH / 4);
    // 6) out = ga @ W_out^T
    {
        dim3 grid(DD / BN, MM / BM);
        tcgemm_out<<<grid, 256, SMEM_BYTES>>>(out);
    }
}

// round 17
// speedup vs baseline: 1.4832x; 1.4832x over previous
#include <cuda_runtime.h>
#include <cuda_bf16.h>
#include <math.h>
#include <stdint.h>

// ---------------- problem dims ----------------
#define NB 8
#define TT 2048
#define DD 1024
#define HH 1536
#define GG 3072              // 2*H
#define MM (NB*TT)           // 16384
#define NCHUNK 16
#define CLEN (TT/NCHUNK)     // 128

// ---------------- scratch ----------------
__device__ float g_u[(size_t)MM*GG];        // u = x @ W_in^T  (gate | xh)
__device__ float g_xc[(size_t)MM*HH];       // conv output fp32
__device__ float g_gp[(size_t)MM*GG];       // gates GEMM out, permuted pairs (forget,inp)
__device__ float2 g_axs[(size_t)MM*HH];     // interleaved (alpha, xs)
__device__ float g_sp[HH];                  // softplus(forget_base)
__device__ float g_carryA[NB*NCHUNK*HH];
__device__ float g_carryH[NB*NCHUNK*HH];
__device__ float g_chunkIn[NB*NCHUNK*HH];
// split-bf16 operand buffers
__device__ __nv_bfloat16 g_ahi[(size_t)MM*HH];
__device__ __nv_bfloat16 g_alo[(size_t)MM*HH];
__device__ __nv_bfloat16 g_bhi[(size_t)GG*HH];
__device__ __nv_bfloat16 g_blo[(size_t)GG*HH];

// ---------------- PTX helpers ----------------
__device__ __forceinline__ uint32_t smem_u32(const void* p) {
    uint32_t a;
    asm("{ .reg .u64 t; cvta.to.shared.u64 t, %1; cvt.u32.u64 %0, t; }" : "=r"(a) : "l"(p));
    return a;
}
__device__ __forceinline__ void ldsm_x4(uint32_t& r0, uint32_t& r1, uint32_t& r2, uint32_t& r3,
                                        uint32_t addr) {
    asm volatile("ldmatrix.sync.aligned.m8n8.x4.shared.b16 {%0,%1,%2,%3}, [%4];"
                 : "=r"(r0), "=r"(r1), "=r"(r2), "=r"(r3) : "r"(addr));
}
__device__ __forceinline__ void mma16816(float* c,
                                         uint32_t a0, uint32_t a1, uint32_t a2, uint32_t a3,
                                         uint32_t b0, uint32_t b1) {
    asm volatile(
        "mma.sync.aligned.m16n8k16.row.col.f32.bf16.bf16.f32 "
        "{%0,%1,%2,%3}, {%4,%5,%6,%7}, {%8,%9}, {%0,%1,%2,%3};"
        : "+f"(c[0]), "+f"(c[1]), "+f"(c[2]), "+f"(c[3])
        : "r"(a0), "r"(a1), "r"(a2), "r"(a3), "r"(b0), "r"(b1));
}
__device__ __forceinline__ void cp_async16(uint32_t saddr, const void* g) {
    asm volatile("cp.async.cg.shared.global [%0], [%1], 16;" :: "r"(saddr), "l"(g));
}
__device__ __forceinline__ void cp_commit() { asm volatile("cp.async.commit_group;"); }
template<int N> __device__ __forceinline__ void cp_wait() {
    asm volatile("cp.async.wait_group %0;" :: "n"(N));
}

// ---------------- split-bf16 TN GEMM: kc-major fused 3-term, wave-ordered ------
// per BK=32 chunk: stage {Ahi, Alo, Bhi, Blo} via cp.async; per kk:
//   8 ldsm (bh, bl, a<-Ahi) -> wave1: 16 mma Ahi*Bhi -> wave2: 16 mma Ahi*Blo
//   4 ldsm (a<-Alo)         -> wave3: 16 mma Alo*Bhi
// acc reuse distance = 16 mma (fixes R16's RAW stall).  12 ldsm : 48 mma.
// block 128x128, 256 threads = 8 warps (2 M x 4 N), warp tile 64x32, 2 CTA/SM
#define BM 128
#define BN 128
#define BK 32
#define SSTR 40                          // smem row stride in bf16 (32 + 8 pad)
#define TILE_BYTES (BM*SSTR*2)           // 10240
#define STAGE_BYTES (4*TILE_BYTES)       // 40960
#define SMEM_BYTES (2*STAGE_BYTES)       // 81920

__device__ __forceinline__ void tn_gemm_body(
    const __nv_bfloat16* __restrict__ Ahi, const __nv_bfloat16* __restrict__ Alo,
    const __nv_bfloat16* __restrict__ Bhi, const __nv_bfloat16* __restrict__ Blo,
    float* __restrict__ C, int Ndim, int Kdim)
{
    extern __shared__ __nv_bfloat16 smem[];

    const int tid = threadIdx.x;
    const int wid = tid >> 5;
    const int lane = tid & 31;
    const int warp_m = wid >> 2;       // 0..1
    const int warp_n = wid & 3;        // 0..3
    const int m0 = blockIdx.y * BM;
    const int n0 = blockIdx.x * BN;

    // loader: per tile 512 uint4 (128 rows x 4); 256 threads -> rows lr, lr+64
    const int lr = tid >> 2;           // 0..63
    const int q0 = tid & 3;
    const uint32_t smem_base = smem_u32(smem);
    const uint32_t soff0 = (uint32_t)((lr      ) * SSTR + q0 * 8) * 2;
    const uint32_t soff1 = (uint32_t)((lr + 64) * SSTR + q0 * 8) * 2;

    float acc[4][4][4];
#pragma unroll
    for (int i = 0; i < 4; i++)
#pragma unroll
        for (int j = 0; j < 4; j++)
#pragma unroll
            for (int v = 0; v < 4; v++) acc[i][j][v] = 0.f;

    const int kcs = Kdim / BK;

    auto issue = [&](int kc) {
        if (kc < kcs) {
            const uint32_t sbase = smem_base + (uint32_t)(kc & 1) * STAGE_BYTES;
            const __nv_bfloat16* srcs[4] = {
                Ahi + (size_t)m0 * Kdim + kc * BK + q0 * 8,
                Alo + (size_t)m0 * Kdim + kc * BK + q0 * 8,
                Bhi + (size_t)n0 * Kdim + kc * BK + q0 * 8,
                Blo + (size_t)n0 * Kdim + kc * BK + q0 * 8
            };
#pragma unroll
            for (int t = 0; t < 4; t++) {
                cp_async16(sbase + (uint32_t)t * TILE_BYTES + soff0,
                           srcs[t] + (size_t)lr * Kdim);
                cp_async16(sbase + (uint32_t)t * TILE_BYTES + soff1,
                           srcs[t] + (size_t)(lr + 64) * Kdim);
            }
        }
        cp_commit();
    };

    // fragment offsets (bytes within a tile)
    const uint32_t afrag = (uint32_t)(((warp_m * 64 + (lane & 15)) * SSTR
                                       + (lane >> 4) * 8) * 2);
    const uint32_t bfrag = (uint32_t)(((warp_n * 32 + (lane & 15)) * SSTR
                                       + (lane >> 4) * 8) * 2);

    issue(0);

    for (int kc = 0; kc < kcs; kc++) {
        cp_wait<0>();          // stage kc landed
        __syncthreads();       // all warps past compute(kc-1) before reusing its buffer
        issue(kc + 1);

        const uint32_t sbase = smem_base + (uint32_t)(kc & 1) * STAGE_BYTES;
        const uint32_t sAhi = sbase + 0 * TILE_BYTES;
        const uint32_t sAlo = sbase + 1 * TILE_BYTES;
        const uint32_t sBhi = sbase + 2 * TILE_BYTES;
        const uint32_t sBlo = sbase + 3 * TILE_BYTES;

#pragma unroll
        for (int kk = 0; kk < 2; kk++) {
            const uint32_t koff = (uint32_t)(kk * 32);   // 16 bf16 = 32 bytes
            uint32_t bh[2][4], bl[2][4];
#pragma unroll
            for (int nb = 0; nb < 2; nb++) {
                ldsm_x4(bh[nb][0], bh[nb][1], bh[nb][2], bh[nb][3],
                        sBhi + bfrag + (uint32_t)(nb * 16 * SSTR * 2) + koff);
                ldsm_x4(bl[nb][0], bl[nb][1], bl[nb][2], bl[nb][3],
                        sBlo + bfrag + (uint32_t)(nb * 16 * SSTR * 2) + koff);
            }
            uint32_t a[4][4];
#pragma unroll
            for (int mi = 0; mi < 4; mi++)
                ldsm_x4(a[mi][0], a[mi][1], a[mi][2], a[mi][3],
                        sAhi + afrag + (uint32_t)(mi * 16 * SSTR * 2) + koff);

            // wave 1: Ahi * Bhi  (16 mma, all distinct accs)
#pragma unroll
            for (int mi = 0; mi < 4; mi++)
#pragma unroll
                for (int nb = 0; nb < 2; nb++) {
                    mma16816(acc[mi][nb * 2 + 0], a[mi][0], a[mi][1], a[mi][2], a[mi][3],
                             bh[nb][0], bh[nb][2]);
                    mma16816(acc[mi][nb * 2 + 1], a[mi][0], a[mi][1], a[mi][2], a[mi][3],
                             bh[nb][1], bh[nb][3]);
                }
            // wave 2: Ahi * Blo  (16 mma, reuse distance 16)
#pragma unroll
            for (int mi = 0; mi < 4; mi++)
#pragma unroll
                for (int nb = 0; nb < 2; nb++) {
                    mma16816(acc[mi][nb * 2 + 0], a[mi][0], a[mi][1], a[mi][2], a[mi][3],
                             bl[nb][0], bl[nb][2]);
                    mma16816(acc[mi][nb * 2 + 1], a[mi][0], a[mi][1], a[mi][2], a[mi][3],
                             bl[nb][1], bl[nb][3]);
                }
            // reload A frags <- Alo
#pragma unroll
            for (int mi = 0; mi < 4; mi++)
                ldsm_x4(a[mi][0], a[mi][1], a[mi][2], a[mi][3],
                        sAlo + afrag + (uint32_t)(mi * 16 * SSTR * 2) + koff);
            // wave 3: Alo * Bhi  (16 mma)
#pragma unroll
            for (int mi = 0; mi < 4; mi++)
#pragma unroll
                for (int nb = 0; nb < 2; nb++) {
                    mma16816(acc[mi][nb * 2 + 0], a[mi][0], a[mi][1], a[mi][2], a[mi][3],
                             bh[nb][0], bh[nb][2]);
                    mma16816(acc[mi][nb * 2 + 1], a[mi][0], a[mi][1], a[mi][2], a[mi][3],
                             bh[nb][1], bh[nb][3]);
                }
        }
    }

    // ---- epilogue: plain coalesced store ----
    const int crow0 = m0 + warp_m * 64 + (lane >> 2);
    const int ccol0 = n0 + warp_n * 32 + (lane & 3) * 2;
#pragma unroll
    for (int mi = 0; mi < 4; mi++) {
#pragma unroll
        for (int ni = 0; ni < 4; ni++) {
            int row = crow0 + mi * 16;
            int col = ccol0 + ni * 8;
            float2 v0, v1;
            v0.x = acc[mi][ni][0]; v0.y = acc[mi][ni][1];
            v1.x = acc[mi][ni][2]; v1.y = acc[mi][ni][3];
            *(float2*)(C + (size_t)row * Ndim + col)       = v0;
            *(float2*)(C + (size_t)(row + 8) * Ndim + col) = v1;
        }
    }
}

__global__ __launch_bounds__(256, 2) void tcgemm_in()
{
    tn_gemm_body(g_ahi, g_alo, g_bhi, g_blo, g_u, GG, DD);
}
__global__ __launch_bounds__(256, 2) void tcgemm_gates()
{
    tn_gemm_body(g_ahi, g_alo, g_bhi, g_blo, g_gp, GG, HH);
}
__global__ __launch_bounds__(256, 2) void tcgemm_out(float* __restrict__ out)
{
    tn_gemm_body(g_ahi, g_alo, g_bhi, g_blo, out, DD, HH);
}

// ---------------- fp32 -> (hi, lo) bf16 split ----------------
__device__ __forceinline__ void split1(float v, __nv_bfloat16& hi, __nv_bfloat16& lo) {
    __nv_bfloat16 h = __float2bfloat16(v);
    hi = h;
    lo = __float2bfloat16(v - __bfloat162float(h));
}
__global__ __launch_bounds__(256) void split_x(const float* __restrict__ x, int n4)
{
    int id = blockIdx.x * blockDim.x + threadIdx.x;
    if (id >= n4) return;
    float4 v = ((const float4*)x)[id];
    __nv_bfloat16 h0, h1, h2, h3, l0, l1, l2, l3;
    split1(v.x, h0, l0); split1(v.y, h1, l1);
    split1(v.z, h2, l2); split1(v.w, h3, l3);
    ((__nv_bfloat162*)g_ahi)[id * 2 + 0] = __nv_bfloat162(h0, h1);
    ((__nv_bfloat162*)g_ahi)[id * 2 + 1] = __nv_bfloat162(h2, h3);
    ((__nv_bfloat162*)g_alo)[id * 2 + 0] = __nv_bfloat162(l0, l1);
    ((__nv_bfloat162*)g_alo)[id * 2 + 1] = __nv_bfloat162(l2, l3);
}
__global__ __launch_bounds__(256) void split_w(const float* __restrict__ w, int n4)
{
    int id = blockIdx.x * blockDim.x + threadIdx.x;
    if (id >= n4) return;
    float4 v = ((const float4*)w)[id];
    __nv_bfloat16 h0, h1, h2, h3, l0, l1, l2, l3;
    split1(v.x, h0, l0); split1(v.y, h1, l1);
    split1(v.z, h2, l2); split1(v.w, h3, l3);
    ((__nv_bfloat162*)g_bhi)[id * 2 + 0] = __nv_bfloat162(h0, h1);
    ((__nv_bfloat162*)g_bhi)[id * 2 + 1] = __nv_bfloat162(h2, h3);
    ((__nv_bfloat162*)g_blo)[id * 2 + 0] = __nv_bfloat162(l0, l1);
    ((__nv_bfloat162*)g_blo)[id * 2 + 1] = __nv_bfloat162(l2, l3);
}
// permuted split for W_gates: dst row 2h = W_gates row h (forget), 2h+1 = row HH+h (inp)
__global__ __launch_bounds__(256) void split_w_gates(const float* __restrict__ w, int n4)
{
    int id = blockIdx.x * blockDim.x + threadIdx.x;
    if (id >= n4) return;
    int e = id * 4;
    int j = e / HH;                    // dst row
    int o = e - j * HH;
    int src = (j & 1) ? (HH + (j >> 1)) : (j >> 1);
    float4 v = *(const float4*)(w + (size_t)src * HH + o);
    __nv_bfloat16 h0, h1, h2, h3, l0, l1, l2, l3;
    split1(v.x, h0, l0); split1(v.y, h1, l1);
    split1(v.z, h2, l2); split1(v.w, h3, l3);
    ((__nv_bfloat162*)g_bhi)[id * 2 + 0] = __nv_bfloat162(h0, h1);
    ((__nv_bfloat162*)g_bhi)[id * 2 + 1] = __nv_bfloat162(h2, h3);
    ((__nv_bfloat162*)g_blo)[id * 2 + 0] = __nv_bfloat162(l0, l1);
    ((__nv_bfloat162*)g_blo)[id * 2 + 1] = __nv_bfloat162(l2, l3);
}
__global__ __launch_bounds__(256) void prep_sp(const float* __restrict__ fb)
{
    int i = blockIdx.x * blockDim.x + threadIdx.x;
    if (i < HH) g_sp[i] = log1pf(expf(fb[i]));
}

// ---------------- causal depthwise conv: 4 timesteps/thread, fused split -------
__global__ __launch_bounds__(256) void conv4_kernel(
    const float* __restrict__ cw, const float* __restrict__ cb)
{
    int id = blockIdx.x * blockDim.x + threadIdx.x;
    if (id >= (MM / 4) * HH) return;
    int h = id % HH;
    int g = id / HH;                   // 0 .. MM/4-1
    int tq = g % (TT / 4);
    int n  = g / (TT / 4);
    int t0 = tq * 4;
    const size_t mrow = (size_t)n * TT;

    float w0 = cw[h * 4 + 0], w1 = cw[h * 4 + 1];
    float w2 = cw[h * 4 + 2], w3 = cw[h * 4 + 3];
    float bb = cb[h];

    float xv[7];
#pragma unroll
    for (int j = 0; j < 7; j++) {
        int t = t0 - 3 + j;
        xv[j] = (t >= 0) ? g_u[(mrow + t) * GG + HH + h] : 0.f;
    }
#pragma unroll
    for (int i = 0; i < 4; i++) {
        float acc = bb + w0 * xv[i] + w1 * xv[i + 1] + w2 * xv[i + 2] + w3 * xv[i + 3];
        size_t idx = (mrow + t0 + i) * HH + h;
        g_xc[idx] = acc;
        __nv_bfloat16 hi, lo;
        split1(acc, hi, lo);
        g_ahi[idx] = hi;
        g_alo[idx] = lo;
    }
}

// ---------------- scan pass 1 with FUSED gate math ----------------
__global__ __launch_bounds__(256) void scan1_gate_kernel(const float* __restrict__ b_gates)
{
    int id = blockIdx.x * blockDim.x + threadIdx.x;
    if (id >= NB * NCHUNK * HH) return;
    int h = id % HH;
    int r = id / HH;
    int c = r % NCHUNK;
    int n = r / NCHUNK;

    const float bf_ = b_gates[h];
    const float bi_ = b_gates[HH + h];
    const float sp8 = -8.f * g_sp[h];

    float arun = 1.f, hrun = 0.f;
    size_t m0 = (size_t)n * TT + c * CLEN;
#pragma unroll 2
    for (int tl = 0; tl < CLEN; tl++) {
        size_t m = m0 + tl;
        float2 fi = ((const float2*)(g_gp + m * GG))[h];   // (forget, inp)
        float f  = fi.x + bf_;
        float iv = fi.y + bi_;
        float sf = 1.f / (1.f + expf(-f));
        float alpha = expf(sp8 * sf);
        float beta  = sqrtf(1.f - alpha * alpha + 1e-6f);
        float si = 1.f / (1.f + expf(-iv));
        size_t idx = m * HH + h;
        float xs = beta * si * g_xc[idx];
        g_axs[idx] = make_float2(alpha, xs);
        hrun = alpha * hrun + xs;
        arun *= alpha;
    }
    g_carryA[id] = arun;
    g_carryH[id] = hrun;
}
__global__ __launch_bounds__(256) void scan2_kernel()
{
    int id = blockIdx.x * blockDim.x + threadIdx.x;
    if (id >= NB * HH) return;
    int h = id % HH;
    int n = id / HH;
    float hin = 0.f;
    for (int c = 0; c < NCHUNK; c++) {
        int j = (n * NCHUNK + c) * HH + h;
        g_chunkIn[j] = hin;
        hin = g_carryA[j] * hin + g_carryH[j];
    }
}
__global__ __launch_bounds__(256) void scan3_kernel()
{
    int id = blockIdx.x * blockDim.x + threadIdx.x;
    if (id >= NB * NCHUNK * HH) return;
    int h = id % HH;
    int r = id / HH;
    int c = r % NCHUNK;
    int n = r / NCHUNK;
    float hrun = g_chunkIn[(n * NCHUNK + c) * HH + h];
    size_t m0 = (size_t)n * TT + c * CLEN;
#pragma unroll 4
    for (int tl = 0; tl < CLEN; tl++) {
        size_t m = m0 + tl;
        size_t idx = m * HH + h;
        float2 ax = g_axs[idx];
        hrun = ax.x * hrun + ax.y;
        float gate = g_u[m * GG + h];
        float ge = 0.5f * gate * (1.f + erff(gate * 0.70710678118654752f));
        float v = ge * hrun;
        __nv_bfloat16 hi, lo;
        split1(v, hi, lo);
        g_ahi[idx] = hi;
        g_alo[idx] = lo;
    }
}

// ---------------- launch ----------------
extern "C" void kernel_launch(void* const* d_in, const int* in_sizes, int n_in,
                              void* d_out, int out_size)
{
    const float* x          = (const float*)d_in[0];
    const float* W_in       = (const float*)d_in[1];
    const float* conv_w     = (const float*)d_in[2];
    const float* conv_b     = (const float*)d_in[3];
    const float* W_gates    = (const float*)d_in[4];
    const float* b_gates    = (const float*)d_in[5];
    const float* forget_b   = (const float*)d_in[6];
    const float* W_out      = (const float*)d_in[7];
    float* out = (float*)d_out;

    // allow >48KB dynamic smem (device-state change, not graph work)
    cudaFuncSetAttribute(tcgemm_in,    cudaFuncAttributeMaxDynamicSharedMemorySize, SMEM_BYTES);
    cudaFuncSetAttribute(tcgemm_gates, cudaFuncAttributeMaxDynamicSharedMemorySize, SMEM_BYTES);
    cudaFuncSetAttribute(tcgemm_out,   cudaFuncAttributeMaxDynamicSharedMemorySize, SMEM_BYTES);

    // 1) splits + softplus precompute
    split_x<<<(MM * DD / 4 + 255) / 256, 256>>>(x, MM * DD / 4);
    split_w<<<(GG * DD / 4 + 255) / 256, 256>>>(W_in, GG * DD / 4);
    prep_sp<<<(HH + 255) / 256, 256>>>(forget_b);
    // 2) u = x @ W_in^T
    {
        dim3 grid(GG / BN, MM / BM);
        tcgemm_in<<<grid, 256, SMEM_BYTES>>>();
    }
    // 3) causal conv (4 timesteps per thread)
    conv4_kernel<<<((MM / 4) * HH + 255) / 256, 256>>>(conv_w, conv_b);
    split_w_gates<<<(GG * HH / 4 + 255) / 256, 256>>>(W_gates, GG * HH / 4);
    // 4) gates GEMM (permuted pairs)
    {
        dim3 grid(GG / BN, MM / BM);
        tcgemm_gates<<<grid, 256, SMEM_BYTES>>>();
    }
    // 5) chunked scan: pass1 fuses gate math; combine; recompute+gelu+split
    scan1_gate_kernel<<<(NB * NCHUNK * HH) / 256, 256>>>(b_gates);
    scan2_kernel<<<(NB * HH + 255) / 256, 256>>>();
    scan3_kernel<<<(NB * NCHUNK * HH) / 256, 256>>>();
    split_w<<<(DD * HH / 4 + 255) / 256, 256>>>(W_out, DD * HH / 4);
    // 6) out = ga @ W_out^T
    {
        dim3 grid(DD / BN, MM / BM);
        tcgemm_out<<<grid, 256, SMEM_BYTES>>>(out);
    }
}